// round 1
// baseline (speedup 1.0000x reference)
#include <cuda_runtime.h>
#include <cstdint>
#include <math.h>

#define NS 400000
#define NTHR 256
#define NB 1563            // ceil(NS/256)
#define NQ 41              // 1 (loss1) + 4*10 stats

// ---------------- device scratch (no allocations allowed) ----------------
__device__ float g_scratch[NB * 48];   // per-block stat partials
__device__ float g_z[3 * NS];          // z components, SoA
__device__ float g_params[48];         // mu(3)+sinv(6)+c(1) per k (40), [40]=loss1+loss3
__device__ float g_esum[NB];           // per-block energy partial sums

// ---------------- helpers ----------------
__device__ __forceinline__ unsigned long long pk2(float a, float b) {
    unsigned long long r;
    asm("mov.b64 %0, {%1, %2};" : "=l"(r) : "f"(a), "f"(b));
    return r;
}
__device__ __forceinline__ void upk(unsigned long long v, float& a, float& b) {
    asm("mov.b64 {%0, %1}, %2;" : "=f"(a), "=f"(b) : "l"(v));
}
// packed 2-wide fp32 FMA (sm_100+): d = a*b + d
__device__ __forceinline__ void ffma2(unsigned long long& d,
                                      unsigned long long a, unsigned long long b) {
    asm("fma.rn.f32x2 %0, %1, %2, %0;" : "+l"(d) : "l"(a), "l"(b));
}
__device__ __forceinline__ float tanh_fast(float x) {
    // tanh(x) = 1 - 2/(exp(2x)+1); safe at +/-inf, ~1e-6 accuracy via MUFU
    float e = __expf(2.0f * x);
    return 1.0f - __fdividef(2.0f, e + 1.0f);
}
__device__ __forceinline__ float warp_sum(float v) {
#pragma unroll
    for (int o = 16; o > 0; o >>= 1) v += __shfl_down_sync(0xffffffffu, v, o);
    return v;
}

// ---------------- K1: forward pass + statistics ----------------
__global__ __launch_bounds__(NTHR) void k1(
    const float* __restrict__ x1,
    const float* __restrict__ ew1, const float* __restrict__ eb1,
    const float* __restrict__ ew2, const float* __restrict__ eb2,
    const float* __restrict__ ew3, const float* __restrict__ eb3,
    const float* __restrict__ dw1, const float* __restrict__ db1,
    const float* __restrict__ dw2, const float* __restrict__ db2,
    const float* __restrict__ dw3, const float* __restrict__ db3,
    const float* __restrict__ tw1, const float* __restrict__ tb1,
    const float* __restrict__ tw2, const float* __restrict__ tb2)
{
    __shared__ __align__(16) float sW1[2048];   // enc_w1 [128][16]
    __shared__ __align__(16) float sW3[2048];   // dec_w3 [16][128]
    __shared__ __align__(16) float sB3[128];    // dec_b3
    __shared__ float sEB1[16], sEW2[128], sEB2[8], sEW3[8];
    __shared__ float sDW1[8], sDB1[8], sDW2[128], sDB2[16];
    __shared__ float sTW1[24], sTB1[8], sTW2[32], sTB2[4];
    __shared__ float sEB3;
    __shared__ float sWred[NQ][8];

    const int tid = threadIdx.x;
    for (int i = tid; i < 2048; i += NTHR) { sW1[i] = ew1[i]; sW3[i] = dw3[i]; }
    if (tid < 128) { sB3[tid] = db3[tid]; sEW2[tid] = ew2[tid]; sDW2[tid] = dw2[tid]; }
    if (tid < 16)  { sEB1[tid] = eb1[tid]; sDB2[tid] = db2[tid]; }
    if (tid < 8)   { sEB2[tid] = eb2[tid]; sEW3[tid] = ew3[tid];
                     sDW1[tid] = dw1[tid]; sDB1[tid] = db1[tid]; sTB1[tid] = tb1[tid]; }
    if (tid < 24)  sTW1[tid] = tw1[tid];
    if (tid < 32)  sTW2[tid] = tw2[tid];
    if (tid < 4)   sTB2[tid] = tb2[tid];
    if (tid == 0)  sEB3 = eb3[0];
    __syncthreads();

    const int n  = blockIdx.x * NTHR + tid;
    const int ns = (n < NS) ? n : (NS - 1);
    const float valid = (n < NS) ? 1.0f : 0.0f;
    const float4* __restrict__ xv = (const float4*)(x1 + (size_t)ns * 128);

    // ---- encoder layer 1 (128->16) with packed f32x2 FMA, plus ||x1||^2 ----
    unsigned long long a2[8];
#pragma unroll
    for (int j = 0; j < 8; j++) a2[j] = 0ull;
    float n1sq = 0.0f;
#pragma unroll 4
    for (int i4 = 0; i4 < 32; i4++) {
        float4 x = xv[i4];
        n1sq += x.x * x.x + x.y * x.y + x.z * x.z + x.w * x.w;
        float xs[4] = {x.x, x.y, x.z, x.w};
#pragma unroll
        for (int c = 0; c < 4; c++) {
            unsigned long long xb = pk2(xs[c], xs[c]);
            const ulonglong2* w = (const ulonglong2*)(sW1 + (i4 * 4 + c) * 16);
            ulonglong2 p0 = w[0], p1 = w[1], p2 = w[2], p3 = w[3];
            ffma2(a2[0], xb, p0.x); ffma2(a2[1], xb, p0.y);
            ffma2(a2[2], xb, p1.x); ffma2(a2[3], xb, p1.y);
            ffma2(a2[4], xb, p2.x); ffma2(a2[5], xb, p2.y);
            ffma2(a2[6], xb, p3.x); ffma2(a2[7], xb, p3.y);
        }
    }
    float h1[16];
#pragma unroll
    for (int j = 0; j < 8; j++) {
        float a, b;
        upk(a2[j], a, b);
        h1[2 * j]     = tanh_fast(a + sEB1[2 * j]);
        h1[2 * j + 1] = tanh_fast(b + sEB1[2 * j + 1]);
    }

    // ---- encoder 16->8->1 ----
    float h2[8];
#pragma unroll
    for (int o = 0; o < 8; o++) {
        float s = sEB2[o];
#pragma unroll
        for (int i = 0; i < 16; i++) s += h1[i] * sEW2[i * 8 + o];
        h2[o] = tanh_fast(s);
    }
    float s3 = sEB3;
#pragma unroll
    for (int i = 0; i < 8; i++) s3 += h2[i] * sEW3[i];
    const float zc0 = tanh_fast(s3);   // z1

    // ---- decoder 1->8->16 ----
    float g1[8];
#pragma unroll
    for (int o = 0; o < 8; o++) g1[o] = tanh_fast(sDB1[o] + zc0 * sDW1[o]);
    unsigned long long gb[16];
#pragma unroll
    for (int o = 0; o < 16; o++) {
        float s = sDB2[o];
#pragma unroll
        for (int i = 0; i < 8; i++) s += g1[i] * sDW2[i * 16 + o];
        float g2 = tanh_fast(s);
        gb[o] = pk2(g2, g2);
    }

    // ---- decoder 16->128 fused with distance accumulation (reload x1, L1-hot) ----
    float dotv = 0.0f, n2sq = 0.0f, dsq = 0.0f;
#pragma unroll 2
    for (int c4 = 0; c4 < 32; c4++) {
        ulonglong2 yb = ((const ulonglong2*)sB3)[c4];
        unsigned long long y0 = yb.x, y1 = yb.y;
#pragma unroll
        for (int j = 0; j < 16; j++) {
            ulonglong2 w = ((const ulonglong2*)(sW3 + j * 128))[c4];
            ffma2(y0, gb[j], w.x);
            ffma2(y1, gb[j], w.y);
        }
        float4 x = xv[c4];
        float ya, yb2, yc, yd;
        upk(y0, ya, yb2);
        upk(y1, yc, yd);
        dotv += x.x * ya + x.y * yb2 + x.z * yc + x.w * yd;
        n2sq += ya * ya + yb2 * yb2 + yc * yc + yd * yd;
        float d0 = x.x - ya, d1 = x.y - yb2, d2 = x.z - yc, d3 = x.w - yd;
        dsq += d0 * d0 + d1 * d1 + d2 * d2 + d3 * d3;
    }

    const float zc1 = dotv / (sqrtf(n1sq) * sqrtf(n2sq));  // dist_cos
    const float zc2 = sqrtf(dsq);                           // dist_euc

    if (n < NS) {
        g_z[n]          = zc0;
        g_z[NS + n]     = zc1;
        g_z[2 * NS + n] = zc2;
    }

    // ---- estimator 3->8->4 + softmax ----
    float gm[4];
    {
        float t[8];
#pragma unroll
        for (int o = 0; o < 8; o++)
            t[o] = tanh_fast(sTB1[o] + zc0 * sTW1[o] + zc1 * sTW1[8 + o] + zc2 * sTW1[16 + o]);
        float lg[4];
#pragma unroll
        for (int k = 0; k < 4; k++) {
            float s = sTB2[k];
#pragma unroll
            for (int o = 0; o < 8; o++) s += t[o] * sTW2[o * 4 + k];
            lg[k] = s;
        }
        float m = fmaxf(fmaxf(lg[0], lg[1]), fmaxf(lg[2], lg[3]));
        float e0 = __expf(lg[0] - m), e1 = __expf(lg[1] - m);
        float e2 = __expf(lg[2] - m), e3 = __expf(lg[3] - m);
        float inv = __fdividef(1.0f, e0 + e1 + e2 + e3) * valid;
        gm[0] = e0 * inv; gm[1] = e1 * inv; gm[2] = e2 * inv; gm[3] = e3 * inv;
    }
    const float dsv = dsq * valid;

    // ---- deterministic block reduction of 41 statistics ----
    const int lane = tid & 31, wid = tid >> 5;
    int cnt = 0;
    {
        float s = warp_sum(dsv);
        if (lane == 0) sWred[cnt][wid] = s;
        cnt++;
    }
#pragma unroll
    for (int k = 0; k < 4; k++) {
        float g = gm[k];
        float vv[10] = {g, g * zc0, g * zc1, g * zc2,
                        g * zc0 * zc0, g * zc0 * zc1, g * zc0 * zc2,
                        g * zc1 * zc1, g * zc1 * zc2, g * zc2 * zc2};
#pragma unroll
        for (int q = 0; q < 10; q++) {
            float s = warp_sum(vv[q]);
            if (lane == 0) sWred[cnt + q][wid] = s;
        }
        cnt += 10;
    }
    __syncthreads();
    if (tid < NQ) {
        float s = 0.0f;
#pragma unroll
        for (int w = 0; w < 8; w++) s += sWred[tid][w];
        g_scratch[blockIdx.x * 48 + tid] = s;
    }
}

// ---------------- K2: global stat reduce + GMM params (double precision) ----------------
__global__ void k2() {
    __shared__ double part[48][8];
    __shared__ double tot[48];
    __shared__ double l3sh[4];
    const int tid = threadIdx.x;           // 384 threads
    const int q = tid >> 3, rep = tid & 7;
    if (q < NQ) {
        double a0 = 0, a1 = 0, a2 = 0, a3 = 0;
        int b = rep;
        for (; b + 24 < NB; b += 32) {
            a0 += (double)g_scratch[b * 48 + q];
            a1 += (double)g_scratch[(b + 8) * 48 + q];
            a2 += (double)g_scratch[(b + 16) * 48 + q];
            a3 += (double)g_scratch[(b + 24) * 48 + q];
        }
        for (; b < NB; b += 8) a0 += (double)g_scratch[b * 48 + q];
        part[q][rep] = a0 + a1 + a2 + a3;
    }
    __syncthreads();
    if (tid < NQ) {
        double t = 0;
#pragma unroll
        for (int r = 0; r < 8; r++) t += part[tid][r];
        tot[tid] = t;
    }
    __syncthreads();
    if (tid < 4) {
        const int k = tid;
        const double* T = tot + 1 + k * 10;
        double S0 = T[0];
        double m0 = T[1] / S0, m1 = T[2] / S0, m2 = T[3] / S0;
        double s00 = T[4] / S0 - m0 * m0, s01 = T[5] / S0 - m0 * m1, s02 = T[6] / S0 - m0 * m2;
        double s11 = T[7] / S0 - m1 * m1, s12 = T[8] / S0 - m1 * m2, s22 = T[9] / S0 - m2 * m2;
        double c00 = s11 * s22 - s12 * s12;
        double c01 = s02 * s12 - s01 * s22;
        double c02 = s01 * s12 - s02 * s11;
        double det = s00 * c00 + s01 * c01 + s02 * c02;
        double inv = 1.0 / det;
        double phi = S0 / (double)NS;
        double ck = log(phi) - 0.5 * (3.0 * log(2.0 * M_PI) + log(det));
        g_params[k * 10 + 0] = (float)m0;
        g_params[k * 10 + 1] = (float)m1;
        g_params[k * 10 + 2] = (float)m2;
        g_params[k * 10 + 3] = (float)(c00 * inv);
        g_params[k * 10 + 4] = (float)(c01 * inv);
        g_params[k * 10 + 5] = (float)(c02 * inv);
        g_params[k * 10 + 6] = (float)((s00 * s22 - s02 * s02) * inv);
        g_params[k * 10 + 7] = (float)((s02 * s01 - s00 * s12) * inv);
        g_params[k * 10 + 8] = (float)((s00 * s11 - s01 * s01) * inv);
        g_params[k * 10 + 9] = (float)ck;
        l3sh[k] = 1.0 / s00 + 1.0 / s11 + 1.0 / s22;
    }
    __syncthreads();
    if (tid == 0) {
        double loss1 = tot[0] / (double)NS;
        g_params[40] = (float)(loss1 + 1e-4 * (l3sh[0] + l3sh[1] + l3sh[2] + l3sh[3]));
    }
}

// ---------------- K3: per-sample energy ----------------
__global__ __launch_bounds__(NTHR) void k3(float* __restrict__ out) {
    __shared__ float p[48];
    __shared__ float sw[8];
    const int tid = threadIdx.x;
    if (tid < 41) p[tid] = g_params[tid];
    __syncthreads();
    const int n = blockIdx.x * NTHR + tid;
    const int ns = (n < NS) ? n : (NS - 1);
    const float zc0 = g_z[ns], zc1 = g_z[NS + ns], zc2 = g_z[2 * NS + ns];
    float e = 0.0f;
#pragma unroll
    for (int k = 0; k < 4; k++) {
        const float* P = p + k * 10;
        float v0 = zc0 - P[0], v1 = zc1 - P[1], v2 = zc2 - P[2];
        float q = v0 * v0 * P[3] + v1 * v1 * P[6] + v2 * v2 * P[8]
                + 2.0f * (v0 * v1 * P[4] + v0 * v2 * P[5] + v1 * v2 * P[7]);
        e += 0.5f * q - P[9];
    }
    if (n < NS) out[n] = e;
    float ev = (n < NS) ? e : 0.0f;
    float s = warp_sum(ev);
    const int lane = tid & 31, wid = tid >> 5;
    if (lane == 0) sw[wid] = s;
    __syncthreads();
    if (tid == 0) {
        float t = 0.0f;
#pragma unroll
        for (int w = 0; w < 8; w++) t += sw[w];
        g_esum[blockIdx.x] = t;
    }
}

// ---------------- K4: final loss ----------------
__global__ void k4(float* __restrict__ out, int out_size) {
    __shared__ double red[256];
    const int tid = threadIdx.x;
    double a = 0.0;
    for (int i = tid; i < NB; i += 256) a += (double)g_esum[i];
    red[tid] = a;
    __syncthreads();
    for (int s = 128; s > 0; s >>= 1) {
        if (tid < s) red[tid] += red[tid + s];
        __syncthreads();
    }
    if (tid == 0 && out_size > NS) {
        out[NS] = g_params[40] + (float)(0.01 * (red[0] / (double)NS));
    }
}

extern "C" void kernel_launch(void* const* d_in, const int* in_sizes, int n_in,
                              void* d_out, int out_size) {
    const float* x1  = (const float*)d_in[0];
    const float* ew1 = (const float*)d_in[1];
    const float* eb1 = (const float*)d_in[2];
    const float* ew2 = (const float*)d_in[3];
    const float* eb2 = (const float*)d_in[4];
    const float* ew3 = (const float*)d_in[5];
    const float* eb3 = (const float*)d_in[6];
    const float* dw1 = (const float*)d_in[7];
    const float* db1 = (const float*)d_in[8];
    const float* dw2 = (const float*)d_in[9];
    const float* db2 = (const float*)d_in[10];
    const float* dw3 = (const float*)d_in[11];
    const float* db3 = (const float*)d_in[12];
    const float* tw1 = (const float*)d_in[13];
    const float* tb1 = (const float*)d_in[14];
    const float* tw2 = (const float*)d_in[15];
    const float* tb2 = (const float*)d_in[16];
    float* out = (float*)d_out;

    k1<<<NB, NTHR>>>(x1, ew1, eb1, ew2, eb2, ew3, eb3,
                     dw1, db1, dw2, db2, dw3, db3,
                     tw1, tb1, tw2, tb2);
    k2<<<1, 384>>>();
    k3<<<NB, NTHR>>>(out);
    k4<<<1, 256>>>(out, out_size);
}

// round 2
// speedup vs baseline: 1.5492x; 1.5492x over previous
#include <cuda_runtime.h>
#include <cstdint>
#include <math.h>

#define NS   400000
#define NTHR 256
#define SPT  2                    // samples per thread in k1
#define NB1  782                  // ceil(NS / (NTHR*SPT))
#define NB3  1563                 // ceil(NS / NTHR) for k3
#define NQ   41                   // 1 (loss1) + 4*10 stats

// ---------------- device scratch (no allocations allowed) ----------------
__device__ float g_Wc[128 * 32];       // fused [enc_w1 | dec_w3^T]
__device__ float g_M[16 * 16];         // dec_w3 @ dec_w3^T
__device__ float g_v[16];              // dec_w3 @ dec_b3
__device__ float g_bb[1];              // ||dec_b3||^2
__device__ float g_scratch[NB1 * 48];  // per-block stat partials
__device__ float g_z[3 * NS];          // z components, SoA
__device__ float g_params[48];         // per-k params + loss partial
__device__ float g_esum[NB3];          // per-block energy partials

typedef unsigned long long ull;

// ---------------- helpers ----------------
__device__ __forceinline__ ull pk2(float a, float b) {
    ull r; asm("mov.b64 %0, {%1, %2};" : "=l"(r) : "f"(a), "f"(b)); return r;
}
__device__ __forceinline__ void upk(ull v, float& a, float& b) {
    asm("mov.b64 {%0, %1}, %2;" : "=f"(a), "=f"(b) : "l"(v));
}
__device__ __forceinline__ void ffma2(ull& d, ull a, ull b) {
    asm("fma.rn.f32x2 %0, %1, %2, %0;" : "+l"(d) : "l"(a), "l"(b));
}
__device__ __forceinline__ float tanh_fast(float x) {
    float e = __expf(2.0f * x);
    return 1.0f - __fdividef(2.0f, e + 1.0f);
}
__device__ __forceinline__ float warp_sum(float v) {
#pragma unroll
    for (int o = 16; o > 0; o >>= 1) v += __shfl_down_sync(0xffffffffu, v, o);
    return v;
}

// ---------------- K0: fold decoder algebra into constants ----------------
__global__ void k0(const float* __restrict__ ew1, const float* __restrict__ dw3,
                   const float* __restrict__ db3) {
    const int tid = threadIdx.x;   // 256
    for (int idx = tid; idx < 4096; idx += 256) {
        int i = idx >> 5, c = idx & 31;
        g_Wc[idx] = (c < 16) ? ew1[i * 16 + c] : dw3[(c - 16) * 128 + i];
    }
    {   // M[j][l] = sum_c dw3[j,c]*dw3[l,c]
        int j = tid >> 4, l = tid & 15;
        float s = 0.0f;
        for (int c = 0; c < 128; c++) s += dw3[j * 128 + c] * dw3[l * 128 + c];
        g_M[tid] = s;
    }
    if (tid < 16) {
        float s = 0.0f;
        for (int c = 0; c < 128; c++) s += dw3[tid * 128 + c] * db3[c];
        g_v[tid] = s;
    }
    if (tid == 16) {
        float s = 0.0f;
        for (int c = 0; c < 128; c++) s += db3[c] * db3[c];
        g_bb[0] = s;
    }
}

// ---------------- K1: fused forward + statistics ----------------
struct TailOut { float z0, z1, z2, dsv, g0, g1, g2, g3; };

__global__ __launch_bounds__(NTHR, 2) void k1(
    const float* __restrict__ x1,
    const float* __restrict__ eb1,
    const float* __restrict__ ew2, const float* __restrict__ eb2,
    const float* __restrict__ ew3, const float* __restrict__ eb3,
    const float* __restrict__ dw1, const float* __restrict__ db1,
    const float* __restrict__ dw2, const float* __restrict__ db2,
    const float* __restrict__ db3,
    const float* __restrict__ tw1, const float* __restrict__ tb1,
    const float* __restrict__ tw2, const float* __restrict__ tb2)
{
    __shared__ __align__(16) float sWc[4096];   // [128][32]
    __shared__ __align__(16) float sM[256];     // [16][16]
    __shared__ __align__(16) float sB3[128];
    __shared__ float sV[16];
    __shared__ float sEB1[16], sEW2[128], sEB2[8], sEW3[8];
    __shared__ float sDW1[8], sDB1[8], sDW2[128], sDB2[16];
    __shared__ float sTW1[24], sTB1[8], sTW2[32], sTB2[4];
    __shared__ float sEB3, sBB;
    __shared__ float sWred[NQ][8];

    const int tid = threadIdx.x;
    {
        const float4* src = (const float4*)g_Wc;
        float4* dst = (float4*)sWc;
        for (int i = tid; i < 1024; i += NTHR) dst[i] = src[i];
    }
    if (tid < 256) sM[tid] = g_M[tid];
    if (tid < 128) { sB3[tid] = db3[tid]; sEW2[tid] = ew2[tid]; sDW2[tid] = dw2[tid]; }
    if (tid < 16)  { sEB1[tid] = eb1[tid]; sDB2[tid] = db2[tid]; sV[tid] = g_v[tid]; }
    if (tid < 8)   { sEB2[tid] = eb2[tid]; sEW3[tid] = ew3[tid];
                     sDW1[tid] = dw1[tid]; sDB1[tid] = db1[tid]; sTB1[tid] = tb1[tid]; }
    if (tid < 24)  sTW1[tid] = tw1[tid];
    if (tid < 32)  sTW2[tid] = tw2[tid];
    if (tid < 4)   sTB2[tid] = tb2[tid];
    if (tid == 0)  { sEB3 = eb3[0]; sBB = g_bb[0]; }
    __syncthreads();

    const int base = blockIdx.x * (NTHR * SPT);
    const int nA = base + tid;
    const int nB = base + NTHR + tid;
    const int nAs = (nA < NS) ? nA : (NS - 1);
    const int nBs = (nB < NS) ? nB : (NS - 1);
    const float vA = (nA < NS) ? 1.0f : 0.0f;
    const float vB = (nB < NS) ? 1.0f : 0.0f;
    const float4* __restrict__ xvA = (const float4*)(x1 + (size_t)nAs * 128);
    const float4* __restrict__ xvB = (const float4*)(x1 + (size_t)nBs * 128);

    // ---- fused 128->32 matvec for BOTH samples + ||x1||^2 + x1.b3 ----
    ull A[16], B[16];
#pragma unroll
    for (int q = 0; q < 16; q++) { A[q] = 0ull; B[q] = 0ull; }
    ull accN = 0ull, accB3 = 0ull;    // (n1sqA, n1sqB), (xb3A, xb3B)

#pragma unroll 4
    for (int i4 = 0; i4 < 32; i4++) {
        float4 xa = xvA[i4];
        float4 xb = xvB[i4];
        float4 b3v = ((const float4*)sB3)[i4];
        float xas[4] = {xa.x, xa.y, xa.z, xa.w};
        float xbs[4] = {xb.x, xb.y, xb.z, xb.w};
        float b3s[4] = {b3v.x, b3v.y, b3v.z, b3v.w};
#pragma unroll
        for (int c = 0; c < 4; c++) {
            ull pa = pk2(xas[c], xas[c]);
            ull pb = pk2(xbs[c], xbs[c]);
            ull pab = pk2(xas[c], xbs[c]);
            ffma2(accN, pab, pab);
            ffma2(accB3, pab, pk2(b3s[c], b3s[c]));
            const ulonglong2* w = (const ulonglong2*)(sWc + (i4 * 4 + c) * 32);
#pragma unroll
            for (int q = 0; q < 4; q++) {
                ulonglong2 t = w[q];
                ffma2(A[2 * q], pa, t.x);     ffma2(A[2 * q + 1], pa, t.y);
                ffma2(B[2 * q], pb, t.x);     ffma2(B[2 * q + 1], pb, t.y);
            }
            const ulonglong2* w2 = w + 4;
#pragma unroll
            for (int q = 0; q < 4; q++) {
                ulonglong2 t = w2[q];
                ffma2(A[8 + 2 * q], pa, t.x); ffma2(A[9 + 2 * q], pa, t.y);
                ffma2(B[8 + 2 * q], pb, t.x); ffma2(B[9 + 2 * q], pb, t.y);
            }
        }
    }
    float n1A, n1B, xb3A, xb3B;
    upk(accN, n1A, n1B);
    upk(accB3, xb3A, xb3B);

    // ---- per-sample tail (small nets + distances via precomputed algebra) ----
    TailOut to[SPT];
#pragma unroll
    for (int s = 0; s < SPT; s++) {
        const ull* U = (s == 0) ? A : B;
        const float n1sq = (s == 0) ? n1A : n1B;
        const float xb3  = (s == 0) ? xb3A : xb3B;
        const float valid = (s == 0) ? vA : vB;
        const int   n     = (s == 0) ? nA : nB;

        float enc[16], t16[16];
#pragma unroll
        for (int q = 0; q < 8; q++) {
            float a, b;
            upk(U[q], a, b);     enc[2 * q] = a; enc[2 * q + 1] = b;
            upk(U[8 + q], a, b); t16[2 * q] = a; t16[2 * q + 1] = b;
        }
        // encoder
        float h1[16];
#pragma unroll
        for (int j = 0; j < 16; j++) h1[j] = tanh_fast(enc[j] + sEB1[j]);
        float h2[8];
#pragma unroll
        for (int o = 0; o < 8; o++) {
            float sm = sEB2[o];
#pragma unroll
            for (int i = 0; i < 16; i++) sm += h1[i] * sEW2[i * 8 + o];
            h2[o] = tanh_fast(sm);
        }
        float s3 = sEB3;
#pragma unroll
        for (int i = 0; i < 8; i++) s3 += h2[i] * sEW3[i];
        const float zc0 = tanh_fast(s3);
        // decoder hidden
        float g1[8];
#pragma unroll
        for (int o = 0; o < 8; o++) g1[o] = tanh_fast(sDB1[o] + zc0 * sDW1[o]);
        float g2[16];
        ull gp[8];
#pragma unroll
        for (int o = 0; o < 16; o++) {
            float sm = sDB2[o];
#pragma unroll
            for (int i = 0; i < 8; i++) sm += g1[i] * sDW2[i * 16 + o];
            g2[o] = tanh_fast(sm);
        }
#pragma unroll
        for (int q = 0; q < 8; q++) gp[q] = pk2(g2[2 * q], g2[2 * q + 1]);

        // dot(x1,x2) and ||x2||^2 via precomputed algebra
        float dotv = xb3;
#pragma unroll
        for (int j = 0; j < 16; j++) dotv += g2[j] * t16[j];
        float n2sq = sBB;
#pragma unroll
        for (int j = 0; j < 16; j++) {
            ull acc = pk2(2.0f * sV[j], 0.0f);
            const ulonglong2* Mr = (const ulonglong2*)(sM + j * 16);
#pragma unroll
            for (int q = 0; q < 4; q++) {
                ulonglong2 m = Mr[q];
                ffma2(acc, gp[2 * q], m.x);
                ffma2(acc, gp[2 * q + 1], m.y);
            }
            float pa, pb; upk(acc, pa, pb);
            n2sq += g2[j] * (pa + pb);
        }
        const float dsq = fmaxf(n1sq - 2.0f * dotv + n2sq, 0.0f);
        const float zc1 = dotv * rsqrtf(n1sq * n2sq);
        const float zc2 = sqrtf(dsq);

        if (n < NS) {
            g_z[n]          = zc0;
            g_z[NS + n]     = zc1;
            g_z[2 * NS + n] = zc2;
        }

        // estimator + softmax
        float tt[8];
#pragma unroll
        for (int o = 0; o < 8; o++)
            tt[o] = tanh_fast(sTB1[o] + zc0 * sTW1[o] + zc1 * sTW1[8 + o] + zc2 * sTW1[16 + o]);
        float lg[4];
#pragma unroll
        for (int k = 0; k < 4; k++) {
            float sm = sTB2[k];
#pragma unroll
            for (int o = 0; o < 8; o++) sm += tt[o] * sTW2[o * 4 + k];
            lg[k] = sm;
        }
        float m = fmaxf(fmaxf(lg[0], lg[1]), fmaxf(lg[2], lg[3]));
        float e0 = __expf(lg[0] - m), e1 = __expf(lg[1] - m);
        float e2 = __expf(lg[2] - m), e3 = __expf(lg[3] - m);
        float inv = __fdividef(1.0f, e0 + e1 + e2 + e3) * valid;
        to[s].z0 = zc0; to[s].z1 = zc1; to[s].z2 = zc2;
        to[s].dsv = dsq * valid;
        to[s].g0 = e0 * inv; to[s].g1 = e1 * inv; to[s].g2 = e2 * inv; to[s].g3 = e3 * inv;
    }

    // ---- deterministic block reduction of 41 statistics (both samples fused) ----
    const int lane = tid & 31, wid = tid >> 5;
    {
        float s = warp_sum(to[0].dsv + to[1].dsv);
        if (lane == 0) sWred[0][wid] = s;
    }
    const float fA[3] = {to[0].z0, to[0].z1, to[0].z2};
    const float fB[3] = {to[1].z0, to[1].z1, to[1].z2};
    const float gA[4] = {to[0].g0, to[0].g1, to[0].g2, to[0].g3};
    const float gB[4] = {to[1].g0, to[1].g1, to[1].g2, to[1].g3};
#pragma unroll
    for (int k = 0; k < 4; k++) {
        float vv[10];
        vv[0] = gA[k] + gB[k];
#pragma unroll
        for (int d = 0; d < 3; d++) vv[1 + d] = gA[k] * fA[d] + gB[k] * fB[d];
        int c = 4;
#pragma unroll
        for (int d = 0; d < 3; d++)
#pragma unroll
            for (int e = d; e < 3; e++)
                vv[c++] = gA[k] * fA[d] * fA[e] + gB[k] * fB[d] * fB[e];
#pragma unroll
        for (int q = 0; q < 10; q++) {
            float s = warp_sum(vv[q]);
            if (lane == 0) sWred[1 + k * 10 + q][wid] = s;
        }
    }
    __syncthreads();
    if (tid < NQ) {
        float s = 0.0f;
#pragma unroll
        for (int w = 0; w < 8; w++) s += sWred[tid][w];
        g_scratch[blockIdx.x * 48 + tid] = s;
    }
}

// ---------------- K2: global stat reduce + GMM params (double) ----------------
__global__ void k2() {
    __shared__ double part[48][8];
    __shared__ double tot[48];
    __shared__ double l3sh[4];
    const int tid = threadIdx.x;           // 384
    const int q = tid >> 3, rep = tid & 7;
    if (q < NQ) {
        double a0 = 0, a1 = 0, a2 = 0, a3 = 0;
        int b = rep;
        for (; b + 24 < NB1; b += 32) {
            a0 += (double)g_scratch[b * 48 + q];
            a1 += (double)g_scratch[(b + 8) * 48 + q];
            a2 += (double)g_scratch[(b + 16) * 48 + q];
            a3 += (double)g_scratch[(b + 24) * 48 + q];
        }
        for (; b < NB1; b += 8) a0 += (double)g_scratch[b * 48 + q];
        part[q][rep] = a0 + a1 + a2 + a3;
    }
    __syncthreads();
    if (tid < NQ) {
        double t = 0;
#pragma unroll
        for (int r = 0; r < 8; r++) t += part[tid][r];
        tot[tid] = t;
    }
    __syncthreads();
    if (tid < 4) {
        const int k = tid;
        const double* T = tot + 1 + k * 10;
        double S0 = T[0];
        double m0 = T[1] / S0, m1 = T[2] / S0, m2 = T[3] / S0;
        double s00 = T[4] / S0 - m0 * m0, s01 = T[5] / S0 - m0 * m1, s02 = T[6] / S0 - m0 * m2;
        double s11 = T[7] / S0 - m1 * m1, s12 = T[8] / S0 - m1 * m2, s22 = T[9] / S0 - m2 * m2;
        double c00 = s11 * s22 - s12 * s12;
        double c01 = s02 * s12 - s01 * s22;
        double c02 = s01 * s12 - s02 * s11;
        double det = s00 * c00 + s01 * c01 + s02 * c02;
        double inv = 1.0 / det;
        double phi = S0 / (double)NS;
        double ck = log(phi) - 0.5 * (3.0 * log(2.0 * M_PI) + log(det));
        g_params[k * 10 + 0] = (float)m0;
        g_params[k * 10 + 1] = (float)m1;
        g_params[k * 10 + 2] = (float)m2;
        g_params[k * 10 + 3] = (float)(c00 * inv);
        g_params[k * 10 + 4] = (float)(c01 * inv);
        g_params[k * 10 + 5] = (float)(c02 * inv);
        g_params[k * 10 + 6] = (float)((s00 * s22 - s02 * s02) * inv);
        g_params[k * 10 + 7] = (float)((s02 * s01 - s00 * s12) * inv);
        g_params[k * 10 + 8] = (float)((s00 * s11 - s01 * s01) * inv);
        g_params[k * 10 + 9] = (float)ck;
        l3sh[k] = 1.0 / s00 + 1.0 / s11 + 1.0 / s22;
    }
    __syncthreads();
    if (tid == 0) {
        double loss1 = tot[0] / (double)NS;
        g_params[40] = (float)(loss1 + 1e-4 * (l3sh[0] + l3sh[1] + l3sh[2] + l3sh[3]));
    }
}

// ---------------- K3: per-sample energy ----------------
__global__ __launch_bounds__(NTHR) void k3(float* __restrict__ out) {
    __shared__ float p[48];
    __shared__ float sw[8];
    const int tid = threadIdx.x;
    if (tid < 41) p[tid] = g_params[tid];
    __syncthreads();
    const int n = blockIdx.x * NTHR + tid;
    const int ns = (n < NS) ? n : (NS - 1);
    const float zc0 = g_z[ns], zc1 = g_z[NS + ns], zc2 = g_z[2 * NS + ns];
    float e = 0.0f;
#pragma unroll
    for (int k = 0; k < 4; k++) {
        const float* P = p + k * 10;
        float v0 = zc0 - P[0], v1 = zc1 - P[1], v2 = zc2 - P[2];
        float q = v0 * v0 * P[3] + v1 * v1 * P[6] + v2 * v2 * P[8]
                + 2.0f * (v0 * v1 * P[4] + v0 * v2 * P[5] + v1 * v2 * P[7]);
        e += 0.5f * q - P[9];
    }
    if (n < NS) out[n] = e;
    float ev = (n < NS) ? e : 0.0f;
    float s = warp_sum(ev);
    const int lane = tid & 31, wid = tid >> 5;
    if (lane == 0) sw[wid] = s;
    __syncthreads();
    if (tid == 0) {
        float t = 0.0f;
#pragma unroll
        for (int w = 0; w < 8; w++) t += sw[w];
        g_esum[blockIdx.x] = t;
    }
}

// ---------------- K4: final loss ----------------
__global__ void k4(float* __restrict__ out, int out_size) {
    __shared__ double red[256];
    const int tid = threadIdx.x;
    double a = 0.0;
    for (int i = tid; i < NB3; i += 256) a += (double)g_esum[i];
    red[tid] = a;
    __syncthreads();
    for (int s = 128; s > 0; s >>= 1) {
        if (tid < s) red[tid] += red[tid + s];
        __syncthreads();
    }
    if (tid == 0 && out_size > NS) {
        out[NS] = g_params[40] + (float)(0.01 * (red[0] / (double)NS));
    }
}

extern "C" void kernel_launch(void* const* d_in, const int* in_sizes, int n_in,
                              void* d_out, int out_size) {
    const float* x1  = (const float*)d_in[0];
    const float* ew1 = (const float*)d_in[1];
    const float* eb1 = (const float*)d_in[2];
    const float* ew2 = (const float*)d_in[3];
    const float* eb2 = (const float*)d_in[4];
    const float* ew3 = (const float*)d_in[5];
    const float* eb3 = (const float*)d_in[6];
    const float* dw1 = (const float*)d_in[7];
    const float* db1 = (const float*)d_in[8];
    const float* dw2 = (const float*)d_in[9];
    const float* db2 = (const float*)d_in[10];
    const float* dw3 = (const float*)d_in[11];
    const float* db3 = (const float*)d_in[12];
    const float* tw1 = (const float*)d_in[13];
    const float* tb1 = (const float*)d_in[14];
    const float* tw2 = (const float*)d_in[15];
    const float* tb2 = (const float*)d_in[16];
    float* out = (float*)d_out;

    k0<<<1, 256>>>(ew1, dw3, db3);
    k1<<<NB1, NTHR>>>(x1, eb1, ew2, eb2, ew3, eb3,
                      dw1, db1, dw2, db2, db3,
                      tw1, tb1, tw2, tb2);
    k2<<<1, 384>>>();
    k3<<<NB3, NTHR>>>(out);
    k4<<<1, 256>>>(out, out_size);
}